// round 12
// baseline (speedup 1.0000x reference)
#include <cuda_runtime.h>
#include <cuda_bf16.h>

// RAM multi-step transformer — R9 structure; pinning moved to the GENERIC
// ld.global path (theory: .nc/texture path ignores L2 eviction hints).
//  * in/out table loads: ld.global + evict_last 1.0 + L2::64B
//    (touched set ~41MB @64B, fits L2 with margin -> cross-replay hits)
//  * state table loads:  ld.global.nc + L2::64B, no hint (neutral)
//  * misses are DRAM random-access bound (~42G req/s) — only hits help.
//
// x: (256,1024) i32 | conn_in: (2048,16) | conn_state: (1024,16) | conn_out: (512,16)
// mem_in: (2048,65536) f32 | mem_state: (1024,65536) f32 | mem_out: (512,65536) f32
// out: (256,512) f32

#define BATCH 256
#define IN_BITS 1024
#define N_IN 2048
#define N_ST 1024
#define N_OUT 512
#define TBL 65536
#define MAX_ITERS 4
#define THREADS 256

__device__ __forceinline__ unsigned long long mk_policy_pin() {
    unsigned long long pol;
    asm("createpolicy.fractional.L2::evict_last.b64 %0, 1.0;" : "=l"(pol));
    return pol;
}
// Pinned in/out table load: GENERIC path + evict_last + 64B fills.
__device__ __forceinline__ float ld_pin64(const float* p, unsigned long long pol) {
    float v;
    asm("ld.global.L2::cache_hint.L2::64B.f32 %0, [%1], %2;"
        : "=f"(v) : "l"(p), "l"(pol));
    return v;
}
// Neutral streaming state load: 64B fills, default replacement.
__device__ __forceinline__ float ld_state64(const float* p) {
    float v;
    asm("ld.global.nc.L2::64B.f32 %0, [%1];" : "=f"(v) : "l"(p));
    return v;
}

// 16-bit address from packed bit-words in shared memory.
__device__ __forceinline__ unsigned gather16(const unsigned* __restrict__ sw,
                                             int4 c0, int4 c1, int4 c2, int4 c3) {
    unsigned a = 0;
    a |= ((sw[c0.x >> 5] >> (c0.x & 31)) & 1u) << 0;
    a |= ((sw[c0.y >> 5] >> (c0.y & 31)) & 1u) << 1;
    a |= ((sw[c0.z >> 5] >> (c0.z & 31)) & 1u) << 2;
    a |= ((sw[c0.w >> 5] >> (c0.w & 31)) & 1u) << 3;
    a |= ((sw[c1.x >> 5] >> (c1.x & 31)) & 1u) << 4;
    a |= ((sw[c1.y >> 5] >> (c1.y & 31)) & 1u) << 5;
    a |= ((sw[c1.z >> 5] >> (c1.z & 31)) & 1u) << 6;
    a |= ((sw[c1.w >> 5] >> (c1.w & 31)) & 1u) << 7;
    a |= ((sw[c2.x >> 5] >> (c2.x & 31)) & 1u) << 8;
    a |= ((sw[c2.y >> 5] >> (c2.y & 31)) & 1u) << 9;
    a |= ((sw[c2.z >> 5] >> (c2.z & 31)) & 1u) << 10;
    a |= ((sw[c2.w >> 5] >> (c2.w & 31)) & 1u) << 11;
    a |= ((sw[c3.x >> 5] >> (c3.x & 31)) & 1u) << 12;
    a |= ((sw[c3.y >> 5] >> (c3.y & 31)) & 1u) << 13;
    a |= ((sw[c3.z >> 5] >> (c3.z & 31)) & 1u) << 14;
    a |= ((sw[c3.w >> 5] >> (c3.w & 31)) & 1u) << 15;
    return a;
}

__global__ __launch_bounds__(THREADS, 2)
void ram_multistep_kernel(
    const int* __restrict__ x,
    const int4* __restrict__ conn_in,
    const int4* __restrict__ conn_state,
    const int4* __restrict__ conn_out,
    const float* __restrict__ mem_in,
    const float* __restrict__ mem_state,
    const float* __restrict__ mem_out,
    float* __restrict__ out)
{
    __shared__ unsigned sx[32];       // 1024 input bits packed
    __shared__ unsigned sbufA[96];    // [0,64) in-bits, [64,96) state bits
    __shared__ unsigned sbufB[96];    // double buffer

    const int b = blockIdx.x;
    const int tid = threadIdx.x;
    const int lane = tid & 31;
    const int warp = tid >> 5;        // 0..7

    const unsigned long long pol_pin = mk_policy_pin();

    // ---- Pack x bits (coalesced, ballot) ----
    #pragma unroll
    for (int r = 0; r < 4; r++) {
        int bit = __ldg(x + b * IN_BITS + r * 256 + tid);
        unsigned w = __ballot_sync(0xFFFFFFFFu, bit != 0);
        if (lane == 0) sx[r * 8 + warp] = w;
    }
    if (tid < 32) sbufA[64 + tid] = 0u;    // initial state = 0 (read by iter 0)
    __syncthreads();

    // ---- Input layer: 2048 neurons, 8 per thread, addr batch then load batch ----
    {
        unsigned addr[8];
        #pragma unroll
        for (int r = 0; r < 8; r++) {
            int n = r * 256 + tid;
            const int4* c = conn_in + n * 4;
            int4 c0 = __ldg(c + 0), c1 = __ldg(c + 1), c2 = __ldg(c + 2), c3 = __ldg(c + 3);
            addr[r] = gather16(sx, c0, c1, c2, c3);
        }
        float v[8];
        #pragma unroll
        for (int r = 0; r < 8; r++) {
            int n = r * 256 + tid;
            v[r] = ld_pin64(mem_in + (size_t)n * TBL + addr[r], pol_pin);
        }
        #pragma unroll
        for (int r = 0; r < 8; r++) {
            unsigned w = __ballot_sync(0xFFFFFFFFu, v[r] > 0.5f);
            if (lane == 0) { sbufA[r * 8 + warp] = w; sbufB[r * 8 + warp] = w; }
        }
    }
    __syncthreads();

    // ---- Recurrent state iterations: 4 per thread, double-buffered, 1 barrier/iter ----
    unsigned* cur = sbufA;
    unsigned* nxt = sbufB;
    for (int it = 0; it < MAX_ITERS; it++) {
        unsigned addr[4];
        #pragma unroll
        for (int k = 0; k < 4; k++) {
            int n = k * 256 + tid;
            const int4* c = conn_state + n * 4;
            int4 c0 = __ldg(c + 0), c1 = __ldg(c + 1), c2 = __ldg(c + 2), c3 = __ldg(c + 3);
            addr[k] = gather16(cur, c0, c1, c2, c3);
        }
        float v[4];
        #pragma unroll
        for (int k = 0; k < 4; k++) {
            int n = k * 256 + tid;
            v[k] = ld_state64(mem_state + (size_t)n * TBL + addr[k]);
        }
        #pragma unroll
        for (int k = 0; k < 4; k++) {
            unsigned w = __ballot_sync(0xFFFFFFFFu, v[k] > 0.5f);
            if (lane == 0) nxt[64 + k * 8 + warp] = w;   // disjoint from cur: no pre-barrier
        }
        __syncthreads();                 // nxt complete & visible
        unsigned* t = cur; cur = nxt; nxt = t;
    }

    // ---- Output layer: 512 neurons, 2 per thread (final state only) ----
    {
        unsigned addr[2];
        #pragma unroll
        for (int r = 0; r < 2; r++) {
            int n = r * 256 + tid;
            const int4* c = conn_out + n * 4;
            int4 c0 = __ldg(c + 0), c1 = __ldg(c + 1), c2 = __ldg(c + 2), c3 = __ldg(c + 3);
            addr[r] = gather16(cur, c0, c1, c2, c3);
        }
        #pragma unroll
        for (int r = 0; r < 2; r++) {
            int n = r * 256 + tid;
            out[b * N_OUT + n] = ld_pin64(mem_out + (size_t)n * TBL + addr[r], pol_pin);
        }
    }
}

extern "C" void kernel_launch(void* const* d_in, const int* in_sizes, int n_in,
                              void* d_out, int out_size) {
    const int* x            = (const int*)d_in[0];
    const int4* conn_in     = (const int4*)d_in[1];
    const int4* conn_state  = (const int4*)d_in[2];
    const int4* conn_out    = (const int4*)d_in[3];
    const float* mem_in     = (const float*)d_in[4];
    const float* mem_state  = (const float*)d_in[5];
    const float* mem_out    = (const float*)d_in[6];
    float* out = (float*)d_out;

    ram_multistep_kernel<<<BATCH, THREADS>>>(x, conn_in, conn_state, conn_out,
                                             mem_in, mem_state, mem_out, out);
}

// round 13
// speedup vs baseline: 1.3125x; 1.3125x over previous
#include <cuda_runtime.h>
#include <cuda_bf16.h>

// RAM multi-step transformer — R8 structure + u16-packed connection tables.
//  * pre-kernel packs conn_in/state/out (i32 -> u16) into a 112KB __device__
//    buffer once per replay: conn load bytes/wavefronts halved (indices<3072).
//  * state conn (4 neurons x 16 u16 = 32 regs) hoisted: loaded once, reused
//    across all 4 iterations, loads overlap the in-phase.
//  * table loads: .nc + cache_hint (evict_last in/out, fractional state) + 64B.
//
// x: (256,1024) i32 | conn_in: (2048,16) | conn_state: (1024,16) | conn_out: (512,16)
// mem_in: (2048,65536) f32 | mem_state: (1024,65536) f32 | mem_out: (512,65536) f32
// out: (256,512) f32

#define BATCH 256
#define IN_BITS 1024
#define N_IN 2048
#define N_ST 1024
#define N_OUT 512
#define TBL 65536
#define MAX_ITERS 4
#define THREADS 256

#define C16_IN 0
#define C16_ST (N_IN * 16)                  // 32768
#define C16_OUT (C16_ST + N_ST * 16)        // 49152
#define C16_TOT (C16_OUT + N_OUT * 16)      // 57344

__device__ unsigned short g_conn16[C16_TOT];

__global__ void pack_conn(const int* __restrict__ ci,
                          const int* __restrict__ cs,
                          const int* __restrict__ co) {
    int i = blockIdx.x * blockDim.x + threadIdx.x;
    if (i < C16_ST)       g_conn16[i] = (unsigned short)ci[i];
    else if (i < C16_OUT) g_conn16[i] = (unsigned short)cs[i - C16_ST];
    else if (i < C16_TOT) g_conn16[i] = (unsigned short)co[i - C16_OUT];
}

__device__ __forceinline__ unsigned long long mk_policy_pin() {
    unsigned long long pol;
    asm("createpolicy.fractional.L2::evict_last.b64 %0, 1.0;" : "=l"(pol));
    return pol;
}
__device__ __forceinline__ unsigned long long mk_policy_state() {
    unsigned long long pol;
    asm("createpolicy.fractional.L2::evict_last.L2::evict_first.b64 %0, 0.25;" : "=l"(pol));
    return pol;
}
__device__ __forceinline__ float ld_tbl64(const float* p, unsigned long long pol) {
    float v;
    asm("ld.global.nc.L2::cache_hint.L2::64B.f32 %0, [%1], %2;"
        : "=f"(v) : "l"(p), "l"(pol));
    return v;
}

__device__ __forceinline__ unsigned bitw(const unsigned* __restrict__ sw, unsigned idx) {
    return (sw[idx >> 5] >> (idx & 31)) & 1u;
}

// 16-bit address from two int4s holding 16 packed u16 indices.
__device__ __forceinline__ unsigned gather16pk(const unsigned* __restrict__ sw,
                                               int4 A, int4 B) {
    unsigned a = 0, w;
    w = (unsigned)A.x; a |= bitw(sw, w & 0xFFFFu) << 0;  a |= bitw(sw, w >> 16) << 1;
    w = (unsigned)A.y; a |= bitw(sw, w & 0xFFFFu) << 2;  a |= bitw(sw, w >> 16) << 3;
    w = (unsigned)A.z; a |= bitw(sw, w & 0xFFFFu) << 4;  a |= bitw(sw, w >> 16) << 5;
    w = (unsigned)A.w; a |= bitw(sw, w & 0xFFFFu) << 6;  a |= bitw(sw, w >> 16) << 7;
    w = (unsigned)B.x; a |= bitw(sw, w & 0xFFFFu) << 8;  a |= bitw(sw, w >> 16) << 9;
    w = (unsigned)B.y; a |= bitw(sw, w & 0xFFFFu) << 10; a |= bitw(sw, w >> 16) << 11;
    w = (unsigned)B.z; a |= bitw(sw, w & 0xFFFFu) << 12; a |= bitw(sw, w >> 16) << 13;
    w = (unsigned)B.w; a |= bitw(sw, w & 0xFFFFu) << 14; a |= bitw(sw, w >> 16) << 15;
    return a;
}

__global__ __launch_bounds__(THREADS, 2)
void ram_multistep_kernel(
    const int* __restrict__ x,
    const float* __restrict__ mem_in,
    const float* __restrict__ mem_state,
    const float* __restrict__ mem_out,
    float* __restrict__ out)
{
    __shared__ unsigned sx[32];       // 1024 input bits packed
    __shared__ unsigned sbufA[96];    // [0,64) in-bits, [64,96) state bits
    __shared__ unsigned sbufB[96];    // double buffer

    const int b = blockIdx.x;
    const int tid = threadIdx.x;
    const int lane = tid & 31;
    const int warp = tid >> 5;        // 0..7

    const unsigned long long pol_pin   = mk_policy_pin();
    const unsigned long long pol_state = mk_policy_state();

    // ---- Pack x bits (coalesced, ballot) ----
    #pragma unroll
    for (int r = 0; r < 4; r++) {
        int bit = __ldg(x + b * IN_BITS + r * 256 + tid);
        unsigned w = __ballot_sync(0xFFFFFFFFu, bit != 0);
        if (lane == 0) sx[r * 8 + warp] = w;
    }
    if (tid < 32) sbufA[64 + tid] = 0u;    // initial state = 0 (read by iter 0)
    __syncthreads();

    // ---- Hoist packed state conn NOW: loads overlap the whole in-phase,
    //      registers reused across all 4 recurrent iterations ----
    int4 cs[8];                            // 4 neurons x 2 int4 (16 u16 each)
    #pragma unroll
    for (int k = 0; k < 4; k++) {
        const int4* cp = (const int4*)(g_conn16 + C16_ST + (size_t)(k * 256 + tid) * 16);
        cs[2 * k]     = __ldg(cp);
        cs[2 * k + 1] = __ldg(cp + 1);
    }

    // ---- Input layer: 2048 neurons, 8 per thread, addr batch then load batch ----
    {
        unsigned addr[8];
        #pragma unroll
        for (int r = 0; r < 8; r++) {
            const int4* cp = (const int4*)(g_conn16 + C16_IN + (size_t)(r * 256 + tid) * 16);
            int4 A = __ldg(cp), B = __ldg(cp + 1);
            addr[r] = gather16pk(sx, A, B);
        }
        float v[8];
        #pragma unroll
        for (int r = 0; r < 8; r++) {
            int n = r * 256 + tid;
            v[r] = ld_tbl64(mem_in + (size_t)n * TBL + addr[r], pol_pin);
        }
        #pragma unroll
        for (int r = 0; r < 8; r++) {
            unsigned w = __ballot_sync(0xFFFFFFFFu, v[r] > 0.5f);
            if (lane == 0) { sbufA[r * 8 + warp] = w; sbufB[r * 8 + warp] = w; }
        }
    }
    __syncthreads();

    // ---- Recurrent state iterations: 4 per thread, double-buffered, 1 barrier/iter ----
    unsigned* cur = sbufA;
    unsigned* nxt = sbufB;
    for (int it = 0; it < MAX_ITERS; it++) {
        unsigned addr[4];
        #pragma unroll
        for (int k = 0; k < 4; k++)
            addr[k] = gather16pk(cur, cs[2 * k], cs[2 * k + 1]);
        float v[4];
        #pragma unroll
        for (int k = 0; k < 4; k++) {
            int n = k * 256 + tid;
            v[k] = ld_tbl64(mem_state + (size_t)n * TBL + addr[k], pol_state);
        }
        #pragma unroll
        for (int k = 0; k < 4; k++) {
            unsigned w = __ballot_sync(0xFFFFFFFFu, v[k] > 0.5f);
            if (lane == 0) nxt[64 + k * 8 + warp] = w;   // disjoint from cur: no pre-barrier
        }
        __syncthreads();                 // nxt complete & visible
        unsigned* t = cur; cur = nxt; nxt = t;
    }

    // ---- Output layer: 512 neurons, 2 per thread (final state only) ----
    {
        unsigned addr[2];
        #pragma unroll
        for (int r = 0; r < 2; r++) {
            const int4* cp = (const int4*)(g_conn16 + C16_OUT + (size_t)(r * 256 + tid) * 16);
            int4 A = __ldg(cp), B = __ldg(cp + 1);
            addr[r] = gather16pk(cur, A, B);
        }
        #pragma unroll
        for (int r = 0; r < 2; r++) {
            int n = r * 256 + tid;
            out[b * N_OUT + n] = ld_tbl64(mem_out + (size_t)n * TBL + addr[r], pol_pin);
        }
    }
}

extern "C" void kernel_launch(void* const* d_in, const int* in_sizes, int n_in,
                              void* d_out, int out_size) {
    const int* x            = (const int*)d_in[0];
    const int* conn_in      = (const int*)d_in[1];
    const int* conn_state   = (const int*)d_in[2];
    const int* conn_out     = (const int*)d_in[3];
    const float* mem_in     = (const float*)d_in[4];
    const float* mem_state  = (const float*)d_in[5];
    const float* mem_out    = (const float*)d_in[6];
    float* out = (float*)d_out;

    pack_conn<<<(C16_TOT + 255) / 256, 256>>>(conn_in, conn_state, conn_out);
    ram_multistep_kernel<<<BATCH, THREADS>>>(x, mem_in, mem_state, mem_out, out);
}

// round 14
// speedup vs baseline: 1.3140x; 1.0012x over previous
#include <cuda_runtime.h>
#include <cuda_bf16.h>

// RAM multi-step transformer — R13 base (u16-packed conn, hoisted state conn,
// L2::64B fills) + DETERMINISTIC fractional pinning of the state table:
// lines with (elem>>4)&3==0 (stable 25% subset, ~17MB) -> evict_last, rest ->
// evict_first. createpolicy.fractional's own split is probabilistic per access
// (different subset every replay -> no retention, cf. R8's zero delta);
// address-hash selection makes the pinned subset identical across replays.
// in/out tables stay evict_last 1.0 (~40MB). Pinned total ~57MB << 126MB L2.
// Also: out-phase conn hoisted into registers before the state loop.

#define BATCH 256
#define IN_BITS 1024
#define N_IN 2048
#define N_ST 1024
#define N_OUT 512
#define TBL 65536
#define MAX_ITERS 4
#define THREADS 256

#define C16_IN 0
#define C16_ST (N_IN * 16)                  // 32768
#define C16_OUT (C16_ST + N_ST * 16)        // 49152
#define C16_TOT (C16_OUT + N_OUT * 16)      // 57344

__device__ unsigned short g_conn16[C16_TOT];

__global__ void pack_conn(const int* __restrict__ ci,
                          const int* __restrict__ cs,
                          const int* __restrict__ co) {
    int i = blockIdx.x * blockDim.x + threadIdx.x;
    if (i < C16_ST)       g_conn16[i] = (unsigned short)ci[i];
    else if (i < C16_OUT) g_conn16[i] = (unsigned short)cs[i - C16_ST];
    else if (i < C16_TOT) g_conn16[i] = (unsigned short)co[i - C16_OUT];
}

__device__ __forceinline__ unsigned long long mk_policy_last() {
    unsigned long long pol;
    asm("createpolicy.fractional.L2::evict_last.b64 %0, 1.0;" : "=l"(pol));
    return pol;
}
__device__ __forceinline__ unsigned long long mk_policy_first() {
    unsigned long long pol;
    asm("createpolicy.fractional.L2::evict_first.b64 %0, 1.0;" : "=l"(pol));
    return pol;
}
__device__ __forceinline__ float ld_tbl64(const float* p, unsigned long long pol) {
    float v;
    asm("ld.global.nc.L2::cache_hint.L2::64B.f32 %0, [%1], %2;"
        : "=f"(v) : "l"(p), "l"(pol));
    return v;
}

__device__ __forceinline__ unsigned bitw(const unsigned* __restrict__ sw, unsigned idx) {
    return (sw[idx >> 5] >> (idx & 31)) & 1u;
}

// 16-bit address from two int4s holding 16 packed u16 indices.
__device__ __forceinline__ unsigned gather16pk(const unsigned* __restrict__ sw,
                                               int4 A, int4 B) {
    unsigned a = 0, w;
    w = (unsigned)A.x; a |= bitw(sw, w & 0xFFFFu) << 0;  a |= bitw(sw, w >> 16) << 1;
    w = (unsigned)A.y; a |= bitw(sw, w & 0xFFFFu) << 2;  a |= bitw(sw, w >> 16) << 3;
    w = (unsigned)A.z; a |= bitw(sw, w & 0xFFFFu) << 4;  a |= bitw(sw, w >> 16) << 5;
    w = (unsigned)A.w; a |= bitw(sw, w & 0xFFFFu) << 6;  a |= bitw(sw, w >> 16) << 7;
    w = (unsigned)B.x; a |= bitw(sw, w & 0xFFFFu) << 8;  a |= bitw(sw, w >> 16) << 9;
    w = (unsigned)B.y; a |= bitw(sw, w & 0xFFFFu) << 10; a |= bitw(sw, w >> 16) << 11;
    w = (unsigned)B.z; a |= bitw(sw, w & 0xFFFFu) << 12; a |= bitw(sw, w >> 16) << 13;
    w = (unsigned)B.w; a |= bitw(sw, w & 0xFFFFu) << 14; a |= bitw(sw, w >> 16) << 15;
    return a;
}

__global__ __launch_bounds__(THREADS, 2)
void ram_multistep_kernel(
    const int* __restrict__ x,
    const float* __restrict__ mem_in,
    const float* __restrict__ mem_state,
    const float* __restrict__ mem_out,
    float* __restrict__ out)
{
    __shared__ unsigned sx[32];       // 1024 input bits packed
    __shared__ unsigned sbufA[96];    // [0,64) in-bits, [64,96) state bits
    __shared__ unsigned sbufB[96];    // double buffer

    const int b = blockIdx.x;
    const int tid = threadIdx.x;
    const int lane = tid & 31;
    const int warp = tid >> 5;        // 0..7

    const unsigned long long pol_pin   = mk_policy_last();
    const unsigned long long pol_first = mk_policy_first();

    // ---- Pack x bits (coalesced, ballot) ----
    #pragma unroll
    for (int r = 0; r < 4; r++) {
        int bit = __ldg(x + b * IN_BITS + r * 256 + tid);
        unsigned w = __ballot_sync(0xFFFFFFFFu, bit != 0);
        if (lane == 0) sx[r * 8 + warp] = w;
    }
    if (tid < 32) sbufA[64 + tid] = 0u;    // initial state = 0 (read by iter 0)
    __syncthreads();

    // ---- Hoist packed state conn: overlaps in-phase, reused across 4 iters ----
    int4 cs[8];                            // 4 neurons x 2 int4 (16 u16 each)
    #pragma unroll
    for (int k = 0; k < 4; k++) {
        const int4* cp = (const int4*)(g_conn16 + C16_ST + (size_t)(k * 256 + tid) * 16);
        cs[2 * k]     = __ldg(cp);
        cs[2 * k + 1] = __ldg(cp + 1);
    }

    // ---- Input layer: 2048 neurons, 8 per thread ----
    {
        unsigned addr[8];
        #pragma unroll
        for (int r = 0; r < 8; r++) {
            const int4* cp = (const int4*)(g_conn16 + C16_IN + (size_t)(r * 256 + tid) * 16);
            int4 A = __ldg(cp), B = __ldg(cp + 1);
            addr[r] = gather16pk(sx, A, B);
        }
        float v[8];
        #pragma unroll
        for (int r = 0; r < 8; r++) {
            int n = r * 256 + tid;
            v[r] = ld_tbl64(mem_in + (size_t)n * TBL + addr[r], pol_pin);
        }
        #pragma unroll
        for (int r = 0; r < 8; r++) {
            unsigned w = __ballot_sync(0xFFFFFFFFu, v[r] > 0.5f);
            if (lane == 0) { sbufA[r * 8 + warp] = w; sbufB[r * 8 + warp] = w; }
        }
    }

    // ---- Hoist out-phase conn (2 neurons x 2 int4) before the state loop ----
    int4 co[4];
    #pragma unroll
    for (int r = 0; r < 2; r++) {
        const int4* cp = (const int4*)(g_conn16 + C16_OUT + (size_t)(r * 256 + tid) * 16);
        co[2 * r]     = __ldg(cp);
        co[2 * r + 1] = __ldg(cp + 1);
    }
    __syncthreads();

    // ---- Recurrent state iterations: 4 per thread, 1 barrier/iter ----
    unsigned* cur = sbufA;
    unsigned* nxt = sbufB;
    for (int it = 0; it < MAX_ITERS; it++) {
        unsigned addr[4];
        #pragma unroll
        for (int k = 0; k < 4; k++)
            addr[k] = gather16pk(cur, cs[2 * k], cs[2 * k + 1]);
        float v[4];
        #pragma unroll
        for (int k = 0; k < 4; k++) {
            int n = k * 256 + tid;
            // Deterministic fractional pinning: stable 25% of 64B lines
            // (same subset every replay) kept evict_last, rest evict_first.
            unsigned long long pol = (((addr[k] >> 4) & 3u) == 0u) ? pol_pin : pol_first;
            v[k] = ld_tbl64(mem_state + (size_t)n * TBL + addr[k], pol);
        }
        #pragma unroll
        for (int k = 0; k < 4; k++) {
            unsigned w = __ballot_sync(0xFFFFFFFFu, v[k] > 0.5f);
            if (lane == 0) nxt[64 + k * 8 + warp] = w;   // disjoint from cur
        }
        __syncthreads();                 // nxt complete & visible
        unsigned* t = cur; cur = nxt; nxt = t;
    }

    // ---- Output layer: 512 neurons, 2 per thread (final state only) ----
    {
        unsigned addr[2];
        #pragma unroll
        for (int r = 0; r < 2; r++)
            addr[r] = gather16pk(cur, co[2 * r], co[2 * r + 1]);
        #pragma unroll
        for (int r = 0; r < 2; r++) {
            int n = r * 256 + tid;
            out[b * N_OUT + n] = ld_tbl64(mem_out + (size_t)n * TBL + addr[r], pol_pin);
        }
    }
}

extern "C" void kernel_launch(void* const* d_in, const int* in_sizes, int n_in,
                              void* d_out, int out_size) {
    const int* x            = (const int*)d_in[0];
    const int* conn_in      = (const int*)d_in[1];
    const int* conn_state   = (const int*)d_in[2];
    const int* conn_out     = (const int*)d_in[3];
    const float* mem_in     = (const float*)d_in[4];
    const float* mem_state  = (const float*)d_in[5];
    const float* mem_out    = (const float*)d_in[6];
    float* out = (float*)d_out;

    pack_conn<<<(C16_TOT + 255) / 256, 256>>>(conn_in, conn_state, conn_out);
    ram_multistep_kernel<<<BATCH, THREADS>>>(x, mem_in, mem_state, mem_out, out);
}